// round 5
// baseline (speedup 1.0000x reference)
#include <cuda_runtime.h>
#include <cstdint>

#define B_  2
#define S_  4096
#define H_  8
#define DH  32
#define DM  256

// Static scratch (allocation-free per harness rules): 4 x 8MB
__device__ float g_Q[B_*H_*S_*DH];
__device__ float g_K[B_*H_*S_*DH];
__device__ float g_V[B_*H_*S_*DH];
__device__ float g_A[(size_t)B_*S_*DM];

// ---- packed f32x2 helpers (Blackwell-only 2x fp32 path) ----
__device__ __forceinline__ unsigned long long pk2(float a, float b){
    unsigned long long r; asm("mov.b64 %0,{%1,%2};" : "=l"(r) : "f"(a), "f"(b)); return r;
}
__device__ __forceinline__ unsigned long long ffma2(unsigned long long a,
                                                    unsigned long long b,
                                                    unsigned long long c){
    unsigned long long d;
    asm("fma.rn.f32x2 %0,%1,%2,%3;" : "=l"(d) : "l"(a), "l"(b), "l"(c));
    return d;
}
__device__ __forceinline__ unsigned long long fmul2(unsigned long long a,
                                                    unsigned long long b){
    unsigned long long d;
    asm("mul.rn.f32x2 %0,%1,%2;" : "=l"(d) : "l"(a), "l"(b));
    return d;
}
__device__ __forceinline__ float2 up2(unsigned long long a){
    float x, y; asm("mov.b64 {%0,%1},%2;" : "=f"(x), "=f"(y) : "l"(a));
    return make_float2(x, y);
}

// ============================================================================
// SGEMM: C[M=8192, N=256] = A @ W (+ optional head-split output layout)
// mode: 0 = final out-proj (A := g_A internally, C = param, plain layout)
//       1/2/3 = projection into g_Q/g_K/g_V with [B,H,S,Dh] split layout
// ============================================================================
__global__ __launch_bounds__(256) void sgemm_kernel(
    const float* __restrict__ A, const float* __restrict__ W,
    float* __restrict__ C, float scale, int mode)
{
    __shared__ __align__(16) float As[16][64];
    __shared__ __align__(16) float Bs[16][64];

    const float* Ain = (mode == 0) ? (const float*)g_A : A;
    float* Cp = (mode == 1) ? g_Q : (mode == 2) ? g_K : (mode == 3) ? g_V : C;

    int t  = threadIdx.x;
    int m0 = blockIdx.y * 64, n0 = blockIdx.x * 64;
    int ar = t >> 2,       ac = (t & 3)  << 2;   // A tile load: 64x16
    int br = t >> 4,       bc = (t & 15) << 2;   // B tile load: 16x64
    int tm = (t >> 4) << 2, tn = (t & 15) << 2;  // 4x4 microtile

    float acc[4][4];
    #pragma unroll
    for (int i = 0; i < 4; i++)
        #pragma unroll
        for (int j = 0; j < 4; j++) acc[i][j] = 0.f;

    for (int k0 = 0; k0 < DM; k0 += 16) {
        float4 av = *(const float4*)(Ain + (size_t)(m0 + ar) * DM + k0 + ac);
        float4 bv = *(const float4*)(W   + (size_t)(k0 + br) * DM + n0 + bc);
        As[ac + 0][ar] = av.x; As[ac + 1][ar] = av.y;
        As[ac + 2][ar] = av.z; As[ac + 3][ar] = av.w;
        *(float4*)&Bs[br][bc] = bv;
        __syncthreads();
        #pragma unroll
        for (int k = 0; k < 16; k++) {
            float4 a = *(const float4*)&As[k][tm];
            float4 b = *(const float4*)&Bs[k][tn];
            acc[0][0] += a.x*b.x; acc[0][1] += a.x*b.y; acc[0][2] += a.x*b.z; acc[0][3] += a.x*b.w;
            acc[1][0] += a.y*b.x; acc[1][1] += a.y*b.y; acc[1][2] += a.y*b.z; acc[1][3] += a.y*b.w;
            acc[2][0] += a.z*b.x; acc[2][1] += a.z*b.y; acc[2][2] += a.z*b.z; acc[2][3] += a.z*b.w;
            acc[3][0] += a.w*b.x; acc[3][1] += a.w*b.y; acc[3][2] += a.w*b.z; acc[3][3] += a.w*b.w;
        }
        __syncthreads();
    }

    #pragma unroll
    for (int i = 0; i < 4; i++) {
        int row = m0 + tm + i;
        #pragma unroll
        for (int j = 0; j < 4; j++) {
            int col = n0 + tn + j;
            float v = acc[i][j] * scale;
            if (mode == 0) {
                Cp[(size_t)row * DM + col] = v;
            } else {
                int b = row >> 12, s = row & 4095;
                int h = col >> 5,  dh = col & 31;
                Cp[(((size_t)(b * H_ + h)) * S_ + s) * DH + dh] = v;
            }
        }
    }
}

// ============================================================================
// Flash attention, fp32, one query row per thread, 32-key smem tiles.
// All inner-product / accumulation math via packed fma.rn.f32x2 (2x fp32).
// mask is int32 (bool promoted by the harness): nonzero -> masked out.
// ============================================================================
__global__ __launch_bounds__(128) void attn_kernel(const int* __restrict__ mask)
{
    __shared__ __align__(16) float Ks[32][32];
    __shared__ __align__(16) float Vs[32][32];

    int t    = threadIdx.x;
    int qrow = blockIdx.x * 128 + t;
    int h    = blockIdx.y, b = blockIdx.z;

    size_t headoff = ((size_t)(b * H_ + h)) * S_ * DH;
    const float* Qp = g_Q + headoff + (size_t)qrow * DH;

    unsigned long long q2[16], O2[16];
    {
        const ulonglong2* p = (const ulonglong2*)Qp;
        #pragma unroll
        for (int i = 0; i < 8; i++) { ulonglong2 v = p[i]; q2[2*i] = v.x; q2[2*i+1] = v.y; }
    }
    #pragma unroll
    for (int i = 0; i < 16; i++) O2[i] = 0ull;

    float m = -1e30f, l = 0.f;
    const float* Kb = g_K + headoff;
    const float* Vb = g_V + headoff;
    const int* mrow = mask + ((size_t)b * S_ + qrow) * S_;

    for (int k0 = 0; k0 < S_; k0 += 32) {
        __syncthreads();
        {   // cooperative K/V tile load: 32x32 floats each, coalesced float4
            const float4* ks = (const float4*)(Kb + (size_t)k0 * DH);
            const float4* vs = (const float4*)(Vb + (size_t)k0 * DH);
            float4* kd = (float4*)Ks; float4* vd = (float4*)Vs;
            kd[t] = ks[t]; kd[t + 128] = ks[t + 128];
            vd[t] = vs[t]; vd[t + 128] = vs[t + 128];
        }
        __syncthreads();

        // Load 32 int32 mask values, compress to a 32-bit bitmask (1 reg).
        unsigned mbits = 0u;
        {
            const int4* mp = (const int4*)(mrow + k0);
            #pragma unroll
            for (int i = 0; i < 8; i++) {
                int4 mv = mp[i];
                mbits |= (mv.x ? 1u : 0u) << (4*i + 0);
                mbits |= (mv.y ? 1u : 0u) << (4*i + 1);
                mbits |= (mv.z ? 1u : 0u) << (4*i + 2);
                mbits |= (mv.w ? 1u : 0u) << (4*i + 3);
            }
        }

        float s[32];
        #pragma unroll
        for (int j = 0; j < 32; j++) {
            unsigned long long acc = 0ull;
            const ulonglong2* kr = (const ulonglong2*)Ks[j];
            #pragma unroll
            for (int i = 0; i < 8; i++) {
                ulonglong2 kv = kr[i];
                acc = ffma2(q2[2*i],   kv.x, acc);
                acc = ffma2(q2[2*i+1], kv.y, acc);
            }
            float2 f = up2(acc);
            float sj = f.x + f.y;
            s[j] = ((mbits >> j) & 1u) ? -1e30f : sj;
        }

        float mt = s[0];
        #pragma unroll
        for (int j = 1; j < 32; j++) mt = fmaxf(mt, s[j]);
        float mnew = fmaxf(m, mt);
        float corr = __expf(m - mnew);

        float psum = 0.f;
        #pragma unroll
        for (int j = 0; j < 32; j++) { float p = __expf(s[j] - mnew); s[j] = p; psum += p; }
        l = l * corr + psum;

        unsigned long long c2 = pk2(corr, corr);
        #pragma unroll
        for (int i = 0; i < 16; i++) O2[i] = fmul2(O2[i], c2);

        #pragma unroll
        for (int j = 0; j < 32; j++) {
            unsigned long long p2 = pk2(s[j], s[j]);
            const ulonglong2* vr = (const ulonglong2*)Vs[j];
            #pragma unroll
            for (int i = 0; i < 8; i++) {
                ulonglong2 vv = vr[i];
                O2[2*i]   = ffma2(p2, vv.x, O2[2*i]);
                O2[2*i+1] = ffma2(p2, vv.y, O2[2*i+1]);
            }
        }
        m = mnew;
    }

    float inv = 1.f / l;
    float* op = g_A + (((size_t)b * S_ + qrow) * H_ + h) * DH;   // [B,S,H,Dh] = [B,S,256]
    #pragma unroll
    for (int i = 0; i < 16; i++) {
        float2 f = up2(O2[i]);
        ((float2*)op)[i] = make_float2(f.x * inv, f.y * inv);
    }
}

// ============================================================================
extern "C" void kernel_launch(void* const* d_in, const int* in_sizes, int n_in,
                              void* d_out, int out_size)
{
    const float* q    = (const float*)d_in[0];
    const float* k    = (const float*)d_in[1];
    const float* v    = (const float*)d_in[2];
    const int*   mask = (const int*)d_in[3];
    const float* wq   = (const float*)d_in[4];
    const float* wk   = (const float*)d_in[5];
    const float* wv   = (const float*)d_in[6];
    const float* wo   = (const float*)d_in[7];

    dim3 gg(DM / 64, (B_ * S_) / 64);   // (4, 128)
    const float qscale = 0.17677669529663688f;  // 1/sqrt(32) folded into Q

    sgemm_kernel<<<gg, 256>>>(q, wq, nullptr, qscale, 1);  // -> g_Q (scaled, split)
    sgemm_kernel<<<gg, 256>>>(k, wk, nullptr, 1.f,    2);  // -> g_K
    sgemm_kernel<<<gg, 256>>>(v, wv, nullptr, 1.f,    3);  // -> g_V

    attn_kernel<<<dim3(S_ / 128, H_, B_), 128>>>(mask);    // -> g_A [B,S,256]

    sgemm_kernel<<<gg, 256>>>(nullptr, wo, (float*)d_out, 1.f, 0);  // g_A @ w_out -> out
}

// round 8
// speedup vs baseline: 1.9454x; 1.9454x over previous
#include <cuda_runtime.h>
#include <cuda_bf16.h>
#include <cstdint>

#define B_  2
#define S_  4096
#define H_  8
#define DH  32
#define DM  256

// Static scratch (allocation-free): bf16 hi/lo QKV (6 x 4MB), A 8MB, mask bits 4MB
__device__ __nv_bfloat16 g_Qh[B_*H_*S_*DH], g_Ql[B_*H_*S_*DH];
__device__ __nv_bfloat16 g_Kh[B_*H_*S_*DH], g_Kl[B_*H_*S_*DH];
__device__ __nv_bfloat16 g_Vh[B_*H_*S_*DH], g_Vl[B_*H_*S_*DH];
__device__ float g_A[(size_t)B_*S_*DM];
__device__ unsigned g_Mb[(size_t)B_*S_*(S_/32)];

// ============================ PTX helpers ===================================
__device__ __forceinline__ uint32_t smem_u32(const void* p){
    uint32_t a; asm("{ .reg .u64 t; cvta.to.shared.u64 t, %1; cvt.u32.u64 %0, t; }"
                    : "=r"(a) : "l"(p)); return a;
}
__device__ __forceinline__ float ex2f(float x){
    float y; asm("ex2.approx.f32 %0, %1;" : "=f"(y) : "f"(x)); return y;
}
__device__ __forceinline__ void mma16816(float& d0, float& d1, float& d2, float& d3,
    uint32_t a0, uint32_t a1, uint32_t a2, uint32_t a3, uint32_t b0, uint32_t b1){
    asm volatile("mma.sync.aligned.m16n8k16.row.col.f32.bf16.bf16.f32 "
        "{%0,%1,%2,%3},{%4,%5,%6,%7},{%8,%9},{%0,%1,%2,%3};"
        : "+f"(d0), "+f"(d1), "+f"(d2), "+f"(d3)
        : "r"(a0), "r"(a1), "r"(a2), "r"(a3), "r"(b0), "r"(b1));
}
#define MMA(D, A, b0, b1) mma16816((D)[0],(D)[1],(D)[2],(D)[3],(A)[0],(A)[1],(A)[2],(A)[3],(b0),(b1))

__device__ __forceinline__ void ldsm_x4(uint32_t& r0, uint32_t& r1, uint32_t& r2, uint32_t& r3, uint32_t a){
    asm volatile("ldmatrix.sync.aligned.m8n8.x4.shared.b16 {%0,%1,%2,%3}, [%4];"
        : "=r"(r0), "=r"(r1), "=r"(r2), "=r"(r3) : "r"(a));
}
__device__ __forceinline__ void ldsm_x4_t(uint32_t& r0, uint32_t& r1, uint32_t& r2, uint32_t& r3, uint32_t a){
    asm volatile("ldmatrix.sync.aligned.m8n8.x4.trans.shared.b16 {%0,%1,%2,%3}, [%4];"
        : "=r"(r0), "=r"(r1), "=r"(r2), "=r"(r3) : "r"(a));
}
__device__ __forceinline__ void cpasync16(uint32_t dst, const void* src){
    asm volatile("cp.async.cg.shared.global [%0], [%1], 16;"
        :: "r"(dst), "l"(__cvta_generic_to_global(src)) : "memory");
}
#define CP_COMMIT() asm volatile("cp.async.commit_group;" ::: "memory")
#define CP_WAIT(N)  asm volatile("cp.async.wait_group %0;" :: "n"(N) : "memory")

// swizzled smem offset within a [128 rows x 64B] region: conflict-free for
// ldmatrix groups of 8 rows at fixed 16B chunk.
__device__ __forceinline__ uint32_t swoff(int row, int c){
    return (uint32_t)row * 64u + (uint32_t)((c ^ ((row >> 1) & 3)) << 4);
}

// ============================================================================
// SGEMM: C[8192,256] = A @ W. mode 0: g_A @ W -> out (fp32).
// modes 1/2/3: project into bf16 hi/lo Q/K/V with [B,H,S,Dh] split layout.
// ============================================================================
__global__ __launch_bounds__(256) void sgemm_kernel(
    const float* __restrict__ A, const float* __restrict__ W,
    float* __restrict__ C, float scale, int mode)
{
    __shared__ __align__(16) float As[16][64];
    __shared__ __align__(16) float Bs[16][64];

    const float* Ain = (mode == 0) ? (const float*)g_A : A;
    __nv_bfloat16* Hp = (mode == 1) ? g_Qh : (mode == 2) ? g_Kh : g_Vh;
    __nv_bfloat16* Lp = (mode == 1) ? g_Ql : (mode == 2) ? g_Kl : g_Vl;

    int t  = threadIdx.x;
    int m0 = blockIdx.y * 64, n0 = blockIdx.x * 64;
    int ar = t >> 2,       ac = (t & 3)  << 2;
    int br = t >> 4,       bc = (t & 15) << 2;
    int tm = (t >> 4) << 2, tn = (t & 15) << 2;

    float acc[4][4];
    #pragma unroll
    for (int i = 0; i < 4; i++)
        #pragma unroll
        for (int j = 0; j < 4; j++) acc[i][j] = 0.f;

    for (int k0 = 0; k0 < DM; k0 += 16) {
        float4 av = *(const float4*)(Ain + (size_t)(m0 + ar) * DM + k0 + ac);
        float4 bv = *(const float4*)(W   + (size_t)(k0 + br) * DM + n0 + bc);
        As[ac + 0][ar] = av.x; As[ac + 1][ar] = av.y;
        As[ac + 2][ar] = av.z; As[ac + 3][ar] = av.w;
        *(float4*)&Bs[br][bc] = bv;
        __syncthreads();
        #pragma unroll
        for (int k = 0; k < 16; k++) {
            float4 a = *(const float4*)&As[k][tm];
            float4 b = *(const float4*)&Bs[k][tn];
            acc[0][0] += a.x*b.x; acc[0][1] += a.x*b.y; acc[0][2] += a.x*b.z; acc[0][3] += a.x*b.w;
            acc[1][0] += a.y*b.x; acc[1][1] += a.y*b.y; acc[1][2] += a.y*b.z; acc[1][3] += a.y*b.w;
            acc[2][0] += a.z*b.x; acc[2][1] += a.z*b.y; acc[2][2] += a.z*b.z; acc[2][3] += a.z*b.w;
            acc[3][0] += a.w*b.x; acc[3][1] += a.w*b.y; acc[3][2] += a.w*b.z; acc[3][3] += a.w*b.w;
        }
        __syncthreads();
    }

    #pragma unroll
    for (int i = 0; i < 4; i++) {
        int row = m0 + tm + i;
        #pragma unroll
        for (int j = 0; j < 4; j++) {
            int col = n0 + tn + j;
            float v = acc[i][j] * scale;
            if (mode == 0) {
                C[(size_t)row * DM + col] = v;
            } else {
                int b = row >> 12, s = row & 4095;
                int hh = col >> 5, dh = col & 31;
                size_t o = (((size_t)(b * H_ + hh)) * S_ + s) * DH + dh;
                __nv_bfloat16 hi = __float2bfloat16(v);
                Hp[o] = hi;
                Lp[o] = __float2bfloat16(v - __bfloat162float(hi));
            }
        }
    }
}

// ============================================================================
// Mask compress: int32 bool -> 1 bit. word w covers mask[32w..32w+31].
// ============================================================================
__global__ __launch_bounds__(256) void mask_compress(const int* __restrict__ mask)
{
    int w = blockIdx.x * 256 + threadIdx.x;
    const int4* p = (const int4*)(mask + (size_t)w * 32);
    unsigned m = 0;
    #pragma unroll
    for (int i = 0; i < 8; i++) {
        int4 v = p[i];
        m |= (v.x ? 1u : 0u) << (4*i + 0);
        m |= (v.y ? 1u : 0u) << (4*i + 1);
        m |= (v.z ? 1u : 0u) << (4*i + 2);
        m |= (v.w ? 1u : 0u) << (4*i + 3);
    }
    g_Mb[w] = m;
}

// ============================================================================
// mma.sync flash attention. CTA = (qtile128, h, b), 128 threads (4 warps).
// Warp owns 32 q-rows. Per 128-key tile: 4 chunks of 32 keys:
//   S(32x32) = Qh.Kh + Ql.Kh + Qh.Kl  (fp32 regs)
//   P = ex2(S) masked (D-frag -> A-frag register reuse, bf16 hi/lo)
//   O(32x32) += Ph.Vh + Pl.Vh + Ph.Vl (fp32 regs, persists all 32 tiles)
// K/V tiles staged via cp.async double buffer, swizzled [128][64B] regions.
// ============================================================================
#define STG_BYTES 32768   // Kh 0 | Kl 8192 | Vh 16384 | Vl 24576

__device__ __forceinline__ void stage_load(uint32_t dst,
    const __nv_bfloat16* Kh, const __nv_bfloat16* Kl,
    const __nv_bfloat16* Vh, const __nv_bfloat16* Vl, int k0, int t)
{
    #pragma unroll
    for (int i = 0; i < 4; i++) {
        int idx = t + 128 * i;
        int row = idx >> 2, c = idx & 3;
        uint32_t so = swoff(row, c);
        size_t gof = (size_t)(k0 + row) * DH;
        cpasync16(dst +     0 + so, (const char*)(Kh + gof) + c*16);
        cpasync16(dst +  8192 + so, (const char*)(Kl + gof) + c*16);
        cpasync16(dst + 16384 + so, (const char*)(Vh + gof) + c*16);
        cpasync16(dst + 24576 + so, (const char*)(Vl + gof) + c*16);
    }
}

__global__ __launch_bounds__(128) void attn_fa(void)
{
    extern __shared__ char smem[];
    uint32_t sb = smem_u32(smem);
    int t = threadIdx.x, lane = t & 31, w = t >> 5;
    int qtile = blockIdx.x, h = blockIdx.y, b = blockIdx.z;
    size_t ho = ((size_t)(b * H_ + h)) * S_ * DH;
    const __nv_bfloat16 *Kh = g_Kh + ho, *Kl = g_Kl + ho;
    const __nv_bfloat16 *Vh = g_Vh + ho, *Vl = g_Vl + ho;

    int g = lane >> 2, cq = lane & 3;
    int qbase = qtile * 128 + w * 32;

    // ---- Q A-fragments (direct gmem loads, once) ----
    uint32_t Ah[2][2][4], Al[2][2][4];
    #pragma unroll
    for (int mi = 0; mi < 2; mi++)
        #pragma unroll
        for (int kk = 0; kk < 2; kk++)
            #pragma unroll
            for (int r = 0; r < 4; r++) {
                int row = qbase + g + 16*mi + 8*(r & 1);
                int kd  = 16*kk + 8*(r >> 1) + 2*cq;
                size_t o = ho + (size_t)row * DH + kd;
                Ah[mi][kk][r] = *(const uint32_t*)(g_Qh + o);
                Al[mi][kk][r] = *(const uint32_t*)(g_Ql + o);
            }

    // ---- mask row pointers (uint4 = 4 chunk-words per 128-key tile) ----
    const uint4* mrp[4];
    #pragma unroll
    for (int i = 0; i < 4; i++) {
        int row = qbase + g + 16*(i >> 1) + 8*(i & 1);
        mrp[i] = (const uint4*)(g_Mb + ((size_t)b * S_ + row) * (S_/32));
    }

    float Od[2][4][4];
    #pragma unroll
    for (int mi = 0; mi < 2; mi++)
        #pragma unroll
        for (int j = 0; j < 4; j++)
            #pragma unroll
            for (int r = 0; r < 4; r++) Od[mi][j][r] = 0.f;
    float ls[4] = {0.f, 0.f, 0.f, 0.f};

    // per-lane ldmatrix geometry
    int rK = (lane & 7) + ((lane >> 4) << 3), cK = (lane >> 3) & 1;   // K (non-trans)
    int rV = (lane & 7) + (((lane >> 3) & 1) << 3), cV = lane >> 4;   // V (trans)

    stage_load(sb, Kh, Kl, Vh, Vl, 0, t);
    CP_COMMIT();

    for (int kt = 0; kt < 32; kt++) {
        uint32_t stg = sb + (uint32_t)(kt & 1) * STG_BYTES;
        if (kt < 31) {
            stage_load(sb + (uint32_t)((kt + 1) & 1) * STG_BYTES, Kh, Kl, Vh, Vl, (kt + 1) * 128, t);
            CP_COMMIT();
            CP_WAIT(1);
        } else {
            CP_WAIT(0);
        }
        __syncthreads();

        uint4 mw[4];
        #pragma unroll
        for (int i = 0; i < 4; i++) mw[i] = mrp[i][kt];

        #pragma unroll
        for (int c = 0; c < 4; c++) {
            // ---- S = Q.K^T (3-term) ----
            float Sd[2][4][4];
            #pragma unroll
            for (int mi = 0; mi < 2; mi++)
                #pragma unroll
                for (int j = 0; j < 4; j++)
                    #pragma unroll
                    for (int r = 0; r < 4; r++) Sd[mi][j][r] = 0.f;

            #pragma unroll
            for (int kk = 0; kk < 2; kk++)
                #pragma unroll
                for (int p = 0; p < 2; p++) {
                    int rr = c*32 + p*16 + rK, ch = 2*kk + cK;
                    uint32_t b0, b1, b2, b3;
                    ldsm_x4(b0, b1, b2, b3, stg + swoff(rr, ch));          // Kh
                    MMA(Sd[0][2*p],   Ah[0][kk], b0, b1);
                    MMA(Sd[1][2*p],   Ah[1][kk], b0, b1);
                    MMA(Sd[0][2*p+1], Ah[0][kk], b2, b3);
                    MMA(Sd[1][2*p+1], Ah[1][kk], b2, b3);
                    MMA(Sd[0][2*p],   Al[0][kk], b0, b1);
                    MMA(Sd[1][2*p],   Al[1][kk], b0, b1);
                    MMA(Sd[0][2*p+1], Al[0][kk], b2, b3);
                    MMA(Sd[1][2*p+1], Al[1][kk], b2, b3);
                    ldsm_x4(b0, b1, b2, b3, stg + 8192 + swoff(rr, ch));   // Kl
                    MMA(Sd[0][2*p],   Ah[0][kk], b0, b1);
                    MMA(Sd[1][2*p],   Ah[1][kk], b0, b1);
                    MMA(Sd[0][2*p+1], Ah[0][kk], b2, b3);
                    MMA(Sd[1][2*p+1], Ah[1][kk], b2, b3);
                }

            // ---- P = ex2(S) masked; pack D-frags -> A-frags (hi/lo) ----
            uint32_t Ph[2][2][4], Pl2[2][2][4];
            #pragma unroll
            for (int mi = 0; mi < 2; mi++)
                #pragma unroll
                for (int u = 0; u < 2; u++) {
                    uint4 mwv = mw[mi*2 + u];
                    unsigned wq = (c == 0) ? mwv.x : (c == 1) ? mwv.y : (c == 2) ? mwv.z : mwv.w;
                    float lacc = 0.f;
                    #pragma unroll
                    for (int j = 0; j < 4; j++) {
                        int bp = 8*j + 2*cq;
                        float p0 = ((wq >> bp) & 1u)     ? 0.f : ex2f(Sd[mi][j][2*u]);
                        float p1 = ((wq >> (bp+1)) & 1u) ? 0.f : ex2f(Sd[mi][j][2*u+1]);
                        lacc += p0 + p1;
                        __nv_bfloat16 h0 = __float2bfloat16(p0), h1 = __float2bfloat16(p1);
                        uint32_t ph = ((uint32_t)__bfloat16_as_ushort(h1) << 16)
                                    | (uint32_t)__bfloat16_as_ushort(h0);
                        float l0 = p0 - __bfloat162float(h0);
                        float l1 = p1 - __bfloat162float(h1);
                        uint32_t pl;
                        asm("cvt.rn.bf16x2.f32 %0, %1, %2;" : "=r"(pl) : "f"(l1), "f"(l0));
                        Ph[mi][j >> 1][(j & 1)*2 + u]  = ph;
                        Pl2[mi][j >> 1][(j & 1)*2 + u] = pl;
                    }
                    ls[mi*2 + u] += lacc;
                }

            // ---- O += P.V (3-term) ----
            #pragma unroll
            for (int kk = 0; kk < 2; kk++)
                #pragma unroll
                for (int p = 0; p < 2; p++) {
                    int rr = c*32 + kk*16 + rV, ch = 2*p + cV;
                    uint32_t b0, b1, b2, b3;
                    ldsm_x4_t(b0, b1, b2, b3, stg + 16384 + swoff(rr, ch)); // Vh
                    MMA(Od[0][2*p],   Ph[0][kk], b0, b1);
                    MMA(Od[1][2*p],   Ph[1][kk], b0, b1);
                    MMA(Od[0][2*p+1], Ph[0][kk], b2, b3);
                    MMA(Od[1][2*p+1], Ph[1][kk], b2, b3);
                    MMA(Od[0][2*p],   Pl2[0][kk], b0, b1);
                    MMA(Od[1][2*p],   Pl2[1][kk], b0, b1);
                    MMA(Od[0][2*p+1], Pl2[0][kk], b2, b3);
                    MMA(Od[1][2*p+1], Pl2[1][kk], b2, b3);
                    ldsm_x4_t(b0, b1, b2, b3, stg + 24576 + swoff(rr, ch)); // Vl
                    MMA(Od[0][2*p],   Ph[0][kk], b0, b1);
                    MMA(Od[1][2*p],   Ph[1][kk], b0, b1);
                    MMA(Od[0][2*p+1], Ph[0][kk], b2, b3);
                    MMA(Od[1][2*p+1], Ph[1][kk], b2, b3);
                }
        }
        __syncthreads();
    }

    // ---- row-sum reduce across the 4 lanes sharing each row; divide; store ----
    #pragma unroll
    for (int i = 0; i < 4; i++) {
        ls[i] += __shfl_xor_sync(0xffffffffu, ls[i], 1);
        ls[i] += __shfl_xor_sync(0xffffffffu, ls[i], 2);
        ls[i] = 1.f / ls[i];
    }
    #pragma unroll
    for (int mi = 0; mi < 2; mi++)
        #pragma unroll
        for (int u = 0; u < 2; u++) {
            int row = qbase + g + 16*mi + 8*u;
            float inv = ls[mi*2 + u];
            #pragma unroll
            for (int j = 0; j < 4; j++) {
                float2 v = make_float2(Od[mi][j][2*u] * inv, Od[mi][j][2*u+1] * inv);
                *(float2*)(g_A + ((size_t)(b * S_ + row)) * DM + h * DH + 8*j + 2*cq) = v;
            }
        }
}

// ============================================================================
extern "C" void kernel_launch(void* const* d_in, const int* in_sizes, int n_in,
                              void* d_out, int out_size)
{
    const float* q    = (const float*)d_in[0];
    const float* k    = (const float*)d_in[1];
    const float* v    = (const float*)d_in[2];
    const int*   mask = (const int*)d_in[3];
    const float* wq   = (const float*)d_in[4];
    const float* wk   = (const float*)d_in[5];
    const float* wv   = (const float*)d_in[6];
    const float* wo   = (const float*)d_in[7];

    dim3 gg(DM / 64, (B_ * S_) / 64);   // (4, 128)
    // fold 1/sqrt(Dh) * log2(e) into Q so P = exp2(S)
    const float qscale = 0.17677669529663688f * 1.4426950408889634f;

    static int smem_set = 0;
    if (!smem_set) {
        cudaFuncSetAttribute(attn_fa, cudaFuncAttributeMaxDynamicSharedMemorySize, 2 * STG_BYTES);
        smem_set = 1;
    }

    sgemm_kernel<<<gg, 256>>>(q, wq, nullptr, qscale, 1);  // -> g_Qh/g_Ql
    sgemm_kernel<<<gg, 256>>>(k, wk, nullptr, 1.f,    2);  // -> g_Kh/g_Kl
    sgemm_kernel<<<gg, 256>>>(v, wv, nullptr, 1.f,    3);  // -> g_Vh/g_Vl
    mask_compress<<<(B_*S_*(S_/32))/256, 256>>>(mask);     // -> g_Mb bits

    attn_fa<<<dim3(S_/128, H_, B_), 128, 2 * STG_BYTES>>>();  // -> g_A [B,S,256]

    sgemm_kernel<<<gg, 256>>>(nullptr, wo, (float*)d_out, 1.f, 0);  // g_A @ w_out -> out
}

// round 12
// speedup vs baseline: 2.9896x; 1.5368x over previous
#include <cuda_runtime.h>
#include <cuda_bf16.h>
#include <cstdint>

#define B_  2
#define S_  4096
#define H_  8
#define DH  32
#define DM  256

// Static scratch (allocation-free): bf16 hi/lo QKV (6 x 4MB), A 8MB, mask bits 4MB
__device__ __nv_bfloat16 g_Qh[B_*H_*S_*DH], g_Ql[B_*H_*S_*DH];
__device__ __nv_bfloat16 g_Kh[B_*H_*S_*DH], g_Kl[B_*H_*S_*DH];
__device__ __nv_bfloat16 g_Vh[B_*H_*S_*DH], g_Vl[B_*H_*S_*DH];
__device__ float g_A[(size_t)B_*S_*DM];
__device__ unsigned g_Mb[(size_t)B_*S_*(S_/32)];

// ============================ PTX helpers ===================================
__device__ __forceinline__ uint32_t smem_u32(const void* p){
    uint32_t a; asm("{ .reg .u64 t; cvta.to.shared.u64 t, %1; cvt.u32.u64 %0, t; }"
                    : "=r"(a) : "l"(p)); return a;
}
__device__ __forceinline__ float ex2f(float x){
    float y; asm("ex2.approx.f32 %0, %1;" : "=f"(y) : "f"(x)); return y;
}
__device__ __forceinline__ uint32_t cvtpk_bf16x2(float hi, float lo){
    uint32_t r; asm("cvt.rn.bf16x2.f32 %0, %1, %2;" : "=r"(r) : "f"(hi), "f"(lo));
    return r;
}
__device__ __forceinline__ void mma16816(float& d0, float& d1, float& d2, float& d3,
    uint32_t a0, uint32_t a1, uint32_t a2, uint32_t a3, uint32_t b0, uint32_t b1){
    asm volatile("mma.sync.aligned.m16n8k16.row.col.f32.bf16.bf16.f32 "
        "{%0,%1,%2,%3},{%4,%5,%6,%7},{%8,%9},{%0,%1,%2,%3};"
        : "+f"(d0), "+f"(d1), "+f"(d2), "+f"(d3)
        : "r"(a0), "r"(a1), "r"(a2), "r"(a3), "r"(b0), "r"(b1));
}
#define MMA(D, A, b0, b1) mma16816((D)[0],(D)[1],(D)[2],(D)[3],(A)[0],(A)[1],(A)[2],(A)[3],(b0),(b1))

__device__ __forceinline__ void ldsm_x4(uint32_t& r0, uint32_t& r1, uint32_t& r2, uint32_t& r3, uint32_t a){
    asm volatile("ldmatrix.sync.aligned.m8n8.x4.shared.b16 {%0,%1,%2,%3}, [%4];"
        : "=r"(r0), "=r"(r1), "=r"(r2), "=r"(r3) : "r"(a));
}
__device__ __forceinline__ void ldsm_x4_t(uint32_t& r0, uint32_t& r1, uint32_t& r2, uint32_t& r3, uint32_t a){
    asm volatile("ldmatrix.sync.aligned.m8n8.x4.trans.shared.b16 {%0,%1,%2,%3}, [%4];"
        : "=r"(r0), "=r"(r1), "=r"(r2), "=r"(r3) : "r"(a));
}
__device__ __forceinline__ void cpasync16(uint32_t dst, const void* src){
    asm volatile("cp.async.cg.shared.global [%0], [%1], 16;"
        :: "r"(dst), "l"(__cvta_generic_to_global(src)) : "memory");
}
#define CP_COMMIT() asm volatile("cp.async.commit_group;" ::: "memory")
#define CP_WAIT(N)  asm volatile("cp.async.wait_group %0;" :: "n"(N) : "memory")

// swizzled smem offset within a [128 rows x 64B] region: conflict-free for
// ldmatrix groups of 8 rows at fixed 16B chunk.
__device__ __forceinline__ uint32_t swoff(int row, int c){
    return (uint32_t)row * 64u + (uint32_t)((c ^ ((row >> 1) & 3)) << 4);
}

// ============================================================================
// SGEMM: C[8192,256] = A @ W. mode 0: g_A @ W -> out (fp32).
// modes 1/2/3: project into bf16 hi/lo Q/K/V with [B,H,S,Dh] split layout.
// ============================================================================
__global__ __launch_bounds__(256) void sgemm_kernel(
    const float* __restrict__ A, const float* __restrict__ W,
    float* __restrict__ C, float scale, int mode)
{
    __shared__ __align__(16) float As[16][64];
    __shared__ __align__(16) float Bs[16][64];

    const float* Ain = (mode == 0) ? (const float*)g_A : A;
    __nv_bfloat16* Hp = (mode == 1) ? g_Qh : (mode == 2) ? g_Kh : g_Vh;
    __nv_bfloat16* Lp = (mode == 1) ? g_Ql : (mode == 2) ? g_Kl : g_Vl;

    int t  = threadIdx.x;
    int m0 = blockIdx.y * 64, n0 = blockIdx.x * 64;
    int ar = t >> 2,       ac = (t & 3)  << 2;
    int br = t >> 4,       bc = (t & 15) << 2;
    int tm = (t >> 4) << 2, tn = (t & 15) << 2;

    float acc[4][4];
    #pragma unroll
    for (int i = 0; i < 4; i++)
        #pragma unroll
        for (int j = 0; j < 4; j++) acc[i][j] = 0.f;

    for (int k0 = 0; k0 < DM; k0 += 16) {
        float4 av = *(const float4*)(Ain + (size_t)(m0 + ar) * DM + k0 + ac);
        float4 bv = *(const float4*)(W   + (size_t)(k0 + br) * DM + n0 + bc);
        As[ac + 0][ar] = av.x; As[ac + 1][ar] = av.y;
        As[ac + 2][ar] = av.z; As[ac + 3][ar] = av.w;
        *(float4*)&Bs[br][bc] = bv;
        __syncthreads();
        #pragma unroll
        for (int k = 0; k < 16; k++) {
            float4 a = *(const float4*)&As[k][tm];
            float4 b = *(const float4*)&Bs[k][tn];
            acc[0][0] += a.x*b.x; acc[0][1] += a.x*b.y; acc[0][2] += a.x*b.z; acc[0][3] += a.x*b.w;
            acc[1][0] += a.y*b.x; acc[1][1] += a.y*b.y; acc[1][2] += a.y*b.z; acc[1][3] += a.y*b.w;
            acc[2][0] += a.z*b.x; acc[2][1] += a.z*b.y; acc[2][2] += a.z*b.z; acc[2][3] += a.z*b.w;
            acc[3][0] += a.w*b.x; acc[3][1] += a.w*b.y; acc[3][2] += a.w*b.z; acc[3][3] += a.w*b.w;
        }
        __syncthreads();
    }

    #pragma unroll
    for (int i = 0; i < 4; i++) {
        int row = m0 + tm + i;
        #pragma unroll
        for (int j = 0; j < 4; j++) {
            int col = n0 + tn + j;
            float v = acc[i][j] * scale;
            if (mode == 0) {
                C[(size_t)row * DM + col] = v;
            } else {
                int b = row >> 12, s = row & 4095;
                int hh = col >> 5, dh = col & 31;
                size_t o = (((size_t)(b * H_ + hh)) * S_ + s) * DH + dh;
                unsigned short hs = __bfloat16_as_ushort(__float2bfloat16(v));
                float fh = __uint_as_float((uint32_t)hs << 16);
                Hp[o] = __ushort_as_bfloat16(hs);
                Lp[o] = __float2bfloat16(v - fh);
            }
        }
    }
}

// ============================================================================
// Mask compress via warp ballot: thread reads 1 int, ballot -> word.
// word w covers mask[32w..32w+31]; ballot bit i = lane i = int 32w+i.
// ============================================================================
__global__ __launch_bounds__(256) void mask_compress(const int* __restrict__ mask)
{
    size_t i = (size_t)blockIdx.x * 256 + threadIdx.x;    // one int per thread
    int v = mask[i];
    unsigned bits = __ballot_sync(0xffffffffu, v != 0);
    if ((threadIdx.x & 31) == 0) g_Mb[i >> 5] = bits;
}

// ============================================================================
// mma.sync flash attention. CTA = (qtile128, h, b), 128 threads (4 warps).
// Warp owns 32 q-rows. Per 128-key tile: 4 chunks of 32 keys:
//   S(32x32) = Qh.Kh + Ql.Kh + Qh.Kl  (fp32 regs)
//   P = ex2(S) masked (D-frag -> A-frag register reuse, bf16 hi/lo)
//   O(32x32) += Ph.Vh + Pl.Vh + Ph.Vl (fp32 regs, persists all 32 tiles)
// K/V tiles staged via cp.async double buffer, swizzled [128][64B] regions.
// ============================================================================
#define STG_BYTES 32768   // Kh 0 | Kl 8192 | Vh 16384 | Vl 24576

__device__ __forceinline__ void stage_load(uint32_t dst,
    const __nv_bfloat16* Kh, const __nv_bfloat16* Kl,
    const __nv_bfloat16* Vh, const __nv_bfloat16* Vl, int k0, int t)
{
    #pragma unroll
    for (int i = 0; i < 4; i++) {
        int idx = t + 128 * i;
        int row = idx >> 2, c = idx & 3;
        uint32_t so = swoff(row, c);
        size_t gof = (size_t)(k0 + row) * DH;
        cpasync16(dst +     0 + so, (const char*)(Kh + gof) + c*16);
        cpasync16(dst +  8192 + so, (const char*)(Kl + gof) + c*16);
        cpasync16(dst + 16384 + so, (const char*)(Vh + gof) + c*16);
        cpasync16(dst + 24576 + so, (const char*)(Vl + gof) + c*16);
    }
}

__global__ __launch_bounds__(128, 2) void attn_fa(void)
{
    extern __shared__ char smem[];
    uint32_t sb = smem_u32(smem);
    int t = threadIdx.x, lane = t & 31, w = t >> 5;
    int qtile = blockIdx.x, h = blockIdx.y, b = blockIdx.z;
    size_t ho = ((size_t)(b * H_ + h)) * S_ * DH;
    const __nv_bfloat16 *Kh = g_Kh + ho, *Kl = g_Kl + ho;
    const __nv_bfloat16 *Vh = g_Vh + ho, *Vl = g_Vl + ho;

    int g = lane >> 2, cq = lane & 3;
    int qbase = qtile * 128 + w * 32;

    // ---- Q A-fragments (direct gmem loads, once) ----
    uint32_t Ah[2][2][4], Al[2][2][4];
    #pragma unroll
    for (int mi = 0; mi < 2; mi++)
        #pragma unroll
        for (int kk = 0; kk < 2; kk++)
            #pragma unroll
            for (int r = 0; r < 4; r++) {
                int row = qbase + g + 16*mi + 8*(r & 1);
                int kd  = 16*kk + 8*(r >> 1) + 2*cq;
                size_t o = ho + (size_t)row * DH + kd;
                Ah[mi][kk][r] = *(const uint32_t*)(g_Qh + o);
                Al[mi][kk][r] = *(const uint32_t*)(g_Ql + o);
            }

    // ---- mask row pointers (uint4 = 4 chunk-words per 128-key tile) ----
    const uint4* mrp[4];
    #pragma unroll
    for (int i = 0; i < 4; i++) {
        int row = qbase + g + 16*(i >> 1) + 8*(i & 1);
        mrp[i] = (const uint4*)(g_Mb + ((size_t)b * S_ + row) * (S_/32));
    }

    float Od[2][4][4];
    #pragma unroll
    for (int mi = 0; mi < 2; mi++)
        #pragma unroll
        for (int j = 0; j < 4; j++)
            #pragma unroll
            for (int r = 0; r < 4; r++) Od[mi][j][r] = 0.f;
    float ls[4] = {0.f, 0.f, 0.f, 0.f};

    // per-lane ldmatrix geometry
    int rK = (lane & 7) + ((lane >> 4) << 3), cK = (lane >> 3) & 1;   // K (non-trans)
    int rV = (lane & 7) + (((lane >> 3) & 1) << 3), cV = lane >> 4;   // V (trans)

    stage_load(sb, Kh, Kl, Vh, Vl, 0, t);
    CP_COMMIT();

    for (int kt = 0; kt < 32; kt++) {
        uint32_t stg = sb + (uint32_t)(kt & 1) * STG_BYTES;
        if (kt < 31) {
            stage_load(sb + (uint32_t)((kt + 1) & 1) * STG_BYTES, Kh, Kl, Vh, Vl, (kt + 1) * 128, t);
            CP_COMMIT();
            CP_WAIT(1);
        } else {
            CP_WAIT(0);
        }
        __syncthreads();

        uint4 mw[4];
        #pragma unroll
        for (int i = 0; i < 4; i++) mw[i] = mrp[i][kt];

        #pragma unroll
        for (int c = 0; c < 4; c++) {
            // ---- S = Q.K^T (3-term) ----
            float Sd[2][4][4];
            #pragma unroll
            for (int mi = 0; mi < 2; mi++)
                #pragma unroll
                for (int j = 0; j < 4; j++)
                    #pragma unroll
                    for (int r = 0; r < 4; r++) Sd[mi][j][r] = 0.f;

            #pragma unroll
            for (int kk = 0; kk < 2; kk++)
                #pragma unroll
                for (int p = 0; p < 2; p++) {
                    int rr = c*32 + p*16 + rK, ch = 2*kk + cK;
                    uint32_t b0, b1, b2, b3;
                    ldsm_x4(b0, b1, b2, b3, stg + swoff(rr, ch));          // Kh
                    MMA(Sd[0][2*p],   Ah[0][kk], b0, b1);
                    MMA(Sd[1][2*p],   Ah[1][kk], b0, b1);
                    MMA(Sd[0][2*p+1], Ah[0][kk], b2, b3);
                    MMA(Sd[1][2*p+1], Ah[1][kk], b2, b3);
                    MMA(Sd[0][2*p],   Al[0][kk], b0, b1);
                    MMA(Sd[1][2*p],   Al[1][kk], b0, b1);
                    MMA(Sd[0][2*p+1], Al[0][kk], b2, b3);
                    MMA(Sd[1][2*p+1], Al[1][kk], b2, b3);
                    ldsm_x4(b0, b1, b2, b3, stg + 8192 + swoff(rr, ch));   // Kl
                    MMA(Sd[0][2*p],   Ah[0][kk], b0, b1);
                    MMA(Sd[1][2*p],   Ah[1][kk], b0, b1);
                    MMA(Sd[0][2*p+1], Ah[0][kk], b2, b3);
                    MMA(Sd[1][2*p+1], Ah[1][kk], b2, b3);
                }

            // ---- P = ex2(S) masked; pack D-frags -> A-frags (hi/lo) ----
            uint32_t Ph[2][2][4], Pl2[2][2][4];
            #pragma unroll
            for (int mi = 0; mi < 2; mi++)
                #pragma unroll
                for (int u = 0; u < 2; u++) {
                    uint4 mwv = mw[mi*2 + u];
                    unsigned wq = (c == 0) ? mwv.x : (c == 1) ? mwv.y : (c == 2) ? mwv.z : mwv.w;
                    float lacc = 0.f;
                    #pragma unroll
                    for (int j = 0; j < 4; j++) {
                        int bp = 8*j + 2*cq;
                        float p0 = ((wq >> bp) & 1u)     ? 0.f : ex2f(Sd[mi][j][2*u]);
                        float p1 = ((wq >> (bp+1)) & 1u) ? 0.f : ex2f(Sd[mi][j][2*u+1]);
                        lacc += p0 + p1;
                        uint32_t ph = cvtpk_bf16x2(p1, p0);
                        float f0 = __uint_as_float(ph << 16);
                        float f1 = __uint_as_float(ph & 0xffff0000u);
                        uint32_t pl = cvtpk_bf16x2(p1 - f1, p0 - f0);
                        Ph[mi][j >> 1][(j & 1)*2 + u]  = ph;
                        Pl2[mi][j >> 1][(j & 1)*2 + u] = pl;
                    }
                    ls[mi*2 + u] += lacc;
                }

            // ---- O += P.V (3-term) ----
            #pragma unroll
            for (int kk = 0; kk < 2; kk++)
                #pragma unroll
                for (int p = 0; p < 2; p++) {
                    int rr = c*32 + kk*16 + rV, ch = 2*p + cV;
                    uint32_t b0, b1, b2, b3;
                    ldsm_x4_t(b0, b1, b2, b3, stg + 16384 + swoff(rr, ch)); // Vh
                    MMA(Od[0][2*p],   Ph[0][kk], b0, b1);
                    MMA(Od[1][2*p],   Ph[1][kk], b0, b1);
                    MMA(Od[0][2*p+1], Ph[0][kk], b2, b3);
                    MMA(Od[1][2*p+1], Ph[1][kk], b2, b3);
                    MMA(Od[0][2*p],   Pl2[0][kk], b0, b1);
                    MMA(Od[1][2*p],   Pl2[1][kk], b0, b1);
                    MMA(Od[0][2*p+1], Pl2[0][kk], b2, b3);
                    MMA(Od[1][2*p+1], Pl2[1][kk], b2, b3);
                    ldsm_x4_t(b0, b1, b2, b3, stg + 24576 + swoff(rr, ch)); // Vl
                    MMA(Od[0][2*p],   Ph[0][kk], b0, b1);
                    MMA(Od[1][2*p],   Ph[1][kk], b0, b1);
                    MMA(Od[0][2*p+1], Ph[0][kk], b2, b3);
                    MMA(Od[1][2*p+1], Ph[1][kk], b2, b3);
                }
        }
        __syncthreads();
    }

    // ---- row-sum reduce across the 4 lanes sharing each row; divide; store ----
    #pragma unroll
    for (int i = 0; i < 4; i++) {
        ls[i] += __shfl_xor_sync(0xffffffffu, ls[i], 1);
        ls[i] += __shfl_xor_sync(0xffffffffu, ls[i], 2);
        ls[i] = 1.f / ls[i];
    }
    #pragma unroll
    for (int mi = 0; mi < 2; mi++)
        #pragma unroll
        for (int u = 0; u < 2; u++) {
            int row = qbase + g + 16*mi + 8*u;
            float inv = ls[mi*2 + u];
            #pragma unroll
            for (int j = 0; j < 4; j++) {
                float2 v = make_float2(Od[mi][j][2*u] * inv, Od[mi][j][2*u+1] * inv);
                *(float2*)(g_A + ((size_t)(b * S_ + row)) * DM + h * DH + 8*j + 2*cq) = v;
            }
        }
}

// ============================================================================
extern "C" void kernel_launch(void* const* d_in, const int* in_sizes, int n_in,
                              void* d_out, int out_size)
{
    const float* q    = (const float*)d_in[0];
    const float* k    = (const float*)d_in[1];
    const float* v    = (const float*)d_in[2];
    const int*   mask = (const int*)d_in[3];
    const float* wq   = (const float*)d_in[4];
    const float* wk   = (const float*)d_in[5];
    const float* wv   = (const float*)d_in[6];
    const float* wo   = (const float*)d_in[7];

    dim3 gg(DM / 64, (B_ * S_) / 64);   // (4, 128)
    // fold 1/sqrt(Dh) * log2(e) into Q so P = exp2(S)
    const float qscale = 0.17677669529663688f * 1.4426950408889634f;

    static int smem_set = 0;
    if (!smem_set) {
        cudaFuncSetAttribute(attn_fa, cudaFuncAttributeMaxDynamicSharedMemorySize, 2 * STG_BYTES);
        smem_set = 1;
    }

    sgemm_kernel<<<gg, 256>>>(q, wq, nullptr, qscale, 1);  // -> g_Qh/g_Ql
    sgemm_kernel<<<gg, 256>>>(k, wk, nullptr, 1.f,    2);  // -> g_Kh/g_Kl
    sgemm_kernel<<<gg, 256>>>(v, wv, nullptr, 1.f,    3);  // -> g_Vh/g_Vl
    mask_compress<<<(B_*S_*S_)/256, 256>>>(mask);          // -> g_Mb bits (ballot)

    attn_fa<<<dim3(S_/128, H_, B_), 128, 2 * STG_BYTES>>>();  // -> g_A [B,S,256]

    sgemm_kernel<<<gg, 256>>>(nullptr, wo, (float*)d_out, 1.f, 0);  // g_A @ w_out -> out
}

// round 16
// speedup vs baseline: 3.6537x; 1.2221x over previous
#include <cuda_runtime.h>
#include <cuda_bf16.h>
#include <cstdint>

#define B_  2
#define S_  4096
#define H_  8
#define DH  32
#define DM  256

// Static scratch (allocation-free)
__device__ __nv_bfloat16 g_Qh[B_*H_*S_*DH], g_Ql[B_*H_*S_*DH];
__device__ __nv_bfloat16 g_Kh[B_*H_*S_*DH], g_Kl[B_*H_*S_*DH];
__device__ __nv_bfloat16 g_Vh[B_*H_*S_*DH], g_Vl[B_*H_*S_*DH];
__device__ float g_A[(size_t)B_*S_*DM];
__device__ unsigned g_Mb[(size_t)B_*S_*(S_/32)];
// pre-split inputs (hi/lo bf16, [B*S, 256] row-major), x3 for q,k,v
__device__ __nv_bfloat16 g_Ih[3u*B_*S_*DM], g_Il[3u*B_*S_*DM];
// pre-split transposed weights ([n][k] bf16), x3 for wq,wk,wv
__device__ __nv_bfloat16 g_Wth[3*DM*DM], g_Wtl[3*DM*DM];

// ============================ PTX helpers ===================================
__device__ __forceinline__ uint32_t smem_u32(const void* p){
    uint32_t a; asm("{ .reg .u64 t; cvta.to.shared.u64 t, %1; cvt.u32.u64 %0, t; }"
                    : "=r"(a) : "l"(p)); return a;
}
__device__ __forceinline__ float ex2f(float x){
    float y; asm("ex2.approx.f32 %0, %1;" : "=f"(y) : "f"(x)); return y;
}
__device__ __forceinline__ uint32_t cvtpk_bf16x2(float hi, float lo){
    uint32_t r; asm("cvt.rn.bf16x2.f32 %0, %1, %2;" : "=r"(r) : "f"(hi), "f"(lo));
    return r;
}
__device__ __forceinline__ void mma16816(float& d0, float& d1, float& d2, float& d3,
    uint32_t a0, uint32_t a1, uint32_t a2, uint32_t a3, uint32_t b0, uint32_t b1){
    asm volatile("mma.sync.aligned.m16n8k16.row.col.f32.bf16.bf16.f32 "
        "{%0,%1,%2,%3},{%4,%5,%6,%7},{%8,%9},{%0,%1,%2,%3};"
        : "+f"(d0), "+f"(d1), "+f"(d2), "+f"(d3)
        : "r"(a0), "r"(a1), "r"(a2), "r"(a3), "r"(b0), "r"(b1));
}
#define MMA(D, A, b0, b1) mma16816((D)[0],(D)[1],(D)[2],(D)[3],(A)[0],(A)[1],(A)[2],(A)[3],(b0),(b1))

__device__ __forceinline__ void ldsm_x4(uint32_t& r0, uint32_t& r1, uint32_t& r2, uint32_t& r3, uint32_t a){
    asm volatile("ldmatrix.sync.aligned.m8n8.x4.shared.b16 {%0,%1,%2,%3}, [%4];"
        : "=r"(r0), "=r"(r1), "=r"(r2), "=r"(r3) : "r"(a));
}
__device__ __forceinline__ void ldsm_x4_t(uint32_t& r0, uint32_t& r1, uint32_t& r2, uint32_t& r3, uint32_t a){
    asm volatile("ldmatrix.sync.aligned.m8n8.x4.trans.shared.b16 {%0,%1,%2,%3}, [%4];"
        : "=r"(r0), "=r"(r1), "=r"(r2), "=r"(r3) : "r"(a));
}
__device__ __forceinline__ void cpasync16(uint32_t dst, const void* src){
    asm volatile("cp.async.cg.shared.global [%0], [%1], 16;"
        :: "r"(dst), "l"(__cvta_generic_to_global(src)) : "memory");
}
#define CP_COMMIT() asm volatile("cp.async.commit_group;" ::: "memory")
#define CP_WAIT(N)  asm volatile("cp.async.wait_group %0;" :: "n"(N) : "memory")

// swizzled smem offset within a [rows x 64B] region (16B-chunk XOR)
__device__ __forceinline__ uint32_t swoff(int row, int c){
    return (uint32_t)row * 64u + (uint32_t)((c ^ ((row >> 1) & 3)) << 4);
}

// ============================================================================
// Prep: split fp32 -> bf16 hi/lo (elementwise, 4 floats/thread)
// ============================================================================
__global__ __launch_bounds__(256) void conv_split(
    const float* __restrict__ src, __nv_bfloat16* __restrict__ dh,
    __nv_bfloat16* __restrict__ dl)
{
    size_t idx = (size_t)blockIdx.x * 256 + threadIdx.x;   // float4 index
    float4 v = ((const float4*)src)[idx];
    uint32_t h0 = cvtpk_bf16x2(v.y, v.x);
    uint32_t h1 = cvtpk_bf16x2(v.w, v.z);
    uint32_t l0 = cvtpk_bf16x2(v.y - __uint_as_float(h0 & 0xffff0000u),
                               v.x - __uint_as_float(h0 << 16));
    uint32_t l1 = cvtpk_bf16x2(v.w - __uint_as_float(h1 & 0xffff0000u),
                               v.z - __uint_as_float(h1 << 16));
    ((uint2*)dh)[idx] = make_uint2(h0, h1);
    ((uint2*)dl)[idx] = make_uint2(l0, l1);
}

// Prep: weight [K=256][N=256] row-major fp32 -> transposed [n][k] bf16 hi/lo
__global__ __launch_bounds__(256) void conv_wt(
    const float* __restrict__ w, __nv_bfloat16* __restrict__ th,
    __nv_bfloat16* __restrict__ tl)
{
    int idx = blockIdx.x * 256 + threadIdx.x;   // 65536
    int k = idx >> 8, n = idx & 255;
    float v = w[idx];
    unsigned short hs = __bfloat16_as_ushort(__float2bfloat16(v));
    float fh = __uint_as_float((uint32_t)hs << 16);
    th[n * DM + k] = __ushort_as_bfloat16(hs);
    tl[n * DM + k] = __float2bfloat16(v - fh);
}

// ============================================================================
// Projection GEMM via mma.sync: C[8192,256] = (Ah+Al) @ (Wh+Wl)^T-stored
// 3-term: Ah.Wh + Al.Wh + Ah.Wl. Writes head-split hi/lo Q/K/V.
// CTA = 64x64 tile, BK=32 double-buffered, 128 threads (4 warps x 16 rows).
// ============================================================================
#define PJ_STG 16384   // Ah 0 | Al 4096 | Wh 8192 | Wl 12288

__device__ __forceinline__ void proj_fill(uint32_t dst,
    const __nv_bfloat16* Ah, const __nv_bfloat16* Al,
    const __nv_bfloat16* Wh, const __nv_bfloat16* Wl,
    int m0, int n0, int k0, int t)
{
    #pragma unroll
    for (int i = 0; i < 2; i++) {
        int idx = t + 128 * i, row = idx >> 2, c = idx & 3;
        uint32_t so = swoff(row, c);
        size_t ao = (size_t)(m0 + row) * DM + k0 + c * 8;
        size_t wo = (size_t)(n0 + row) * DM + k0 + c * 8;
        cpasync16(dst +     0 + so, Ah + ao);
        cpasync16(dst +  4096 + so, Al + ao);
        cpasync16(dst +  8192 + so, Wh + wo);
        cpasync16(dst + 12288 + so, Wl + wo);
    }
}

__global__ __launch_bounds__(128) void pmma_proj(
    const __nv_bfloat16* __restrict__ Ah, const __nv_bfloat16* __restrict__ Al,
    const __nv_bfloat16* __restrict__ Wh, const __nv_bfloat16* __restrict__ Wl,
    float scale, int mode)
{
    __shared__ __align__(16) char ps[2][PJ_STG];
    uint32_t sb = smem_u32(ps);
    int t = threadIdx.x, lane = t & 31, w = t >> 5;
    int n0 = blockIdx.x * 64, m0 = blockIdx.y * 64;

    // A-frag lane geometry (matrix order m0k0,m8k0,m0k8,m8k8)
    int rA = (lane & 7) + (((lane >> 3) & 1) << 3), cA = lane >> 4;
    // B-frag lane geometry (n-major rows, like attention K)
    int rK = (lane & 7) + ((lane >> 4) << 3), cK = (lane >> 3) & 1;
    int g = lane >> 2, cq = lane & 3;

    float acc[8][4];
    #pragma unroll
    for (int j = 0; j < 8; j++)
        #pragma unroll
        for (int r = 0; r < 4; r++) acc[j][r] = 0.f;

    proj_fill(sb, Ah, Al, Wh, Wl, m0, n0, 0, t);
    CP_COMMIT();

    for (int s = 0; s < 8; s++) {
        uint32_t stg = sb + (uint32_t)(s & 1) * PJ_STG;
        if (s < 7) {
            proj_fill(sb + (uint32_t)((s + 1) & 1) * PJ_STG, Ah, Al, Wh, Wl,
                      m0, n0, (s + 1) * 32, t);
            CP_COMMIT();
            CP_WAIT(1);
        } else {
            CP_WAIT(0);
        }
        __syncthreads();

        #pragma unroll
        for (int kk = 0; kk < 2; kk++) {
            uint32_t ah[4], al[4];
            ldsm_x4(ah[0], ah[1], ah[2], ah[3], stg +        swoff(w*16 + rA, 2*kk + cA));
            ldsm_x4(al[0], al[1], al[2], al[3], stg + 4096 + swoff(w*16 + rA, 2*kk + cA));
            #pragma unroll
            for (int nb = 0; nb < 4; nb++) {
                uint32_t b0, b1, b2, b3;
                ldsm_x4(b0, b1, b2, b3, stg + 8192 + swoff(nb*16 + rK, 2*kk + cK));   // Wh
                MMA(acc[2*nb],   ah, b0, b1);
                MMA(acc[2*nb+1], ah, b2, b3);
                MMA(acc[2*nb],   al, b0, b1);
                MMA(acc[2*nb+1], al, b2, b3);
                ldsm_x4(b0, b1, b2, b3, stg + 12288 + swoff(nb*16 + rK, 2*kk + cK));  // Wl
                MMA(acc[2*nb],   ah, b0, b1);
                MMA(acc[2*nb+1], ah, b2, b3);
            }
        }
        __syncthreads();
    }

    __nv_bfloat16* Hout = (mode == 1) ? g_Qh : (mode == 2) ? g_Kh : g_Vh;
    __nv_bfloat16* Lout = (mode == 1) ? g_Ql : (mode == 2) ? g_Kl : g_Vl;

    #pragma unroll
    for (int u = 0; u < 2; u++) {
        int row = m0 + w*16 + g + 8*u;
        int b = row >> 12, sr = row & 4095;
        #pragma unroll
        for (int j = 0; j < 8; j++) {
            int col = n0 + 8*j + 2*cq;
            int hh = col >> 5, dh = col & 31;
            float f0 = acc[j][2*u]   * scale;
            float f1 = acc[j][2*u+1] * scale;
            uint32_t ph = cvtpk_bf16x2(f1, f0);
            uint32_t pl = cvtpk_bf16x2(f1 - __uint_as_float(ph & 0xffff0000u),
                                       f0 - __uint_as_float(ph << 16));
            size_t o = (((size_t)(b * H_ + hh)) * S_ + sr) * DH + dh;
            *(uint32_t*)(Hout + o) = ph;
            *(uint32_t*)(Lout + o) = pl;
        }
    }
}

// ============================================================================
// Out-projection (scalar fp32, unchanged): d_out = g_A @ w_out
// ============================================================================
__global__ __launch_bounds__(256) void sgemm_out(
    const float* __restrict__ W, float* __restrict__ C)
{
    __shared__ __align__(16) float As[16][64];
    __shared__ __align__(16) float Bs[16][64];

    const float* Ain = (const float*)g_A;
    int t  = threadIdx.x;
    int m0 = blockIdx.y * 64, n0 = blockIdx.x * 64;
    int ar = t >> 2,       ac = (t & 3)  << 2;
    int br = t >> 4,       bc = (t & 15) << 2;
    int tm = (t >> 4) << 2, tn = (t & 15) << 2;

    float acc[4][4];
    #pragma unroll
    for (int i = 0; i < 4; i++)
        #pragma unroll
        for (int j = 0; j < 4; j++) acc[i][j] = 0.f;

    for (int k0 = 0; k0 < DM; k0 += 16) {
        float4 av = *(const float4*)(Ain + (size_t)(m0 + ar) * DM + k0 + ac);
        float4 bv = *(const float4*)(W   + (size_t)(k0 + br) * DM + n0 + bc);
        As[ac + 0][ar] = av.x; As[ac + 1][ar] = av.y;
        As[ac + 2][ar] = av.z; As[ac + 3][ar] = av.w;
        *(float4*)&Bs[br][bc] = bv;
        __syncthreads();
        #pragma unroll
        for (int k = 0; k < 16; k++) {
            float4 a = *(const float4*)&As[k][tm];
            float4 b = *(const float4*)&Bs[k][tn];
            acc[0][0] += a.x*b.x; acc[0][1] += a.x*b.y; acc[0][2] += a.x*b.z; acc[0][3] += a.x*b.w;
            acc[1][0] += a.y*b.x; acc[1][1] += a.y*b.y; acc[1][2] += a.y*b.z; acc[1][3] += a.y*b.w;
            acc[2][0] += a.z*b.x; acc[2][1] += a.z*b.y; acc[2][2] += a.z*b.z; acc[2][3] += a.z*b.w;
            acc[3][0] += a.w*b.x; acc[3][1] += a.w*b.y; acc[3][2] += a.w*b.z; acc[3][3] += a.w*b.w;
        }
        __syncthreads();
    }

    #pragma unroll
    for (int i = 0; i < 4; i++)
        #pragma unroll
        for (int j = 0; j < 4; j++)
            C[(size_t)(m0 + tm + i) * DM + n0 + tn + j] = acc[i][j];
}

// ============================================================================
// Mask compress v3: int4/thread -> nibble -> shuffle-OR within 8-lane groups.
// ============================================================================
__global__ __launch_bounds__(256) void mask_compress(const int* __restrict__ mask)
{
    size_t i4 = (size_t)blockIdx.x * 256 + threadIdx.x;   // int4 index
    int4 v = ((const int4*)mask)[i4];
    unsigned nib = (v.x ? 1u : 0u) | (v.y ? 2u : 0u) | (v.z ? 4u : 0u) | (v.w ? 8u : 0u);
    unsigned lane = threadIdx.x & 31u;
    unsigned bits = nib << (4u * (lane & 7u));
    bits |= __shfl_xor_sync(0xffffffffu, bits, 1);
    bits |= __shfl_xor_sync(0xffffffffu, bits, 2);
    bits |= __shfl_xor_sync(0xffffffffu, bits, 4);
    if ((lane & 7u) == 0u) g_Mb[i4 >> 3] = bits;
}

// ============================================================================
// mma.sync flash attention (unchanged from R8 winner).
// ============================================================================
#define STG_BYTES 32768   // Kh 0 | Kl 8192 | Vh 16384 | Vl 24576

__device__ __forceinline__ void stage_load(uint32_t dst,
    const __nv_bfloat16* Kh, const __nv_bfloat16* Kl,
    const __nv_bfloat16* Vh, const __nv_bfloat16* Vl, int k0, int t)
{
    #pragma unroll
    for (int i = 0; i < 4; i++) {
        int idx = t + 128 * i;
        int row = idx >> 2, c = idx & 3;
        uint32_t so = swoff(row, c);
        size_t gof = (size_t)(k0 + row) * DH;
        cpasync16(dst +     0 + so, (const char*)(Kh + gof) + c*16);
        cpasync16(dst +  8192 + so, (const char*)(Kl + gof) + c*16);
        cpasync16(dst + 16384 + so, (const char*)(Vh + gof) + c*16);
        cpasync16(dst + 24576 + so, (const char*)(Vl + gof) + c*16);
    }
}

__global__ __launch_bounds__(128, 2) void attn_fa(void)
{
    extern __shared__ char smem[];
    uint32_t sb = smem_u32(smem);
    int t = threadIdx.x, lane = t & 31, w = t >> 5;
    int qtile = blockIdx.x, h = blockIdx.y, b = blockIdx.z;
    size_t ho = ((size_t)(b * H_ + h)) * S_ * DH;
    const __nv_bfloat16 *Kh = g_Kh + ho, *Kl = g_Kl + ho;
    const __nv_bfloat16 *Vh = g_Vh + ho, *Vl = g_Vl + ho;

    int g = lane >> 2, cq = lane & 3;
    int qbase = qtile * 128 + w * 32;

    uint32_t Ah[2][2][4], Al[2][2][4];
    #pragma unroll
    for (int mi = 0; mi < 2; mi++)
        #pragma unroll
        for (int kk = 0; kk < 2; kk++)
            #pragma unroll
            for (int r = 0; r < 4; r++) {
                int row = qbase + g + 16*mi + 8*(r & 1);
                int kd  = 16*kk + 8*(r >> 1) + 2*cq;
                size_t o = ho + (size_t)row * DH + kd;
                Ah[mi][kk][r] = *(const uint32_t*)(g_Qh + o);
                Al[mi][kk][r] = *(const uint32_t*)(g_Ql + o);
            }

    const uint4* mrp[4];
    #pragma unroll
    for (int i = 0; i < 4; i++) {
        int row = qbase + g + 16*(i >> 1) + 8*(i & 1);
        mrp[i] = (const uint4*)(g_Mb + ((size_t)b * S_ + row) * (S_/32));
    }

    float Od[2][4][4];
    #pragma unroll
    for (int mi = 0; mi < 2; mi++)
        #pragma unroll
        for (int j = 0; j < 4; j++)
            #pragma unroll
            for (int r = 0; r < 4; r++) Od[mi][j][r] = 0.f;
    float ls[4] = {0.f, 0.f, 0.f, 0.f};

    int rK = (lane & 7) + ((lane >> 4) << 3), cK = (lane >> 3) & 1;
    int rV = (lane & 7) + (((lane >> 3) & 1) << 3), cV = lane >> 4;

    stage_load(sb, Kh, Kl, Vh, Vl, 0, t);
    CP_COMMIT();

    for (int kt = 0; kt < 32; kt++) {
        uint32_t stg = sb + (uint32_t)(kt & 1) * STG_BYTES;
        if (kt < 31) {
            stage_load(sb + (uint32_t)((kt + 1) & 1) * STG_BYTES, Kh, Kl, Vh, Vl, (kt + 1) * 128, t);
            CP_COMMIT();
            CP_WAIT(1);
        } else {
            CP_WAIT(0);
        }
        __syncthreads();

        uint4 mw[4];
        #pragma unroll
        for (int i = 0; i < 4; i++) mw[i] = mrp[i][kt];

        #pragma unroll
        for (int c = 0; c < 4; c++) {
            float Sd[2][4][4];
            #pragma unroll
            for (int mi = 0; mi < 2; mi++)
                #pragma unroll
                for (int j = 0; j < 4; j++)
                    #pragma unroll
                    for (int r = 0; r < 4; r++) Sd[mi][j][r] = 0.f;

            #pragma unroll
            for (int kk = 0; kk < 2; kk++)
                #pragma unroll
                for (int p = 0; p < 2; p++) {
                    int rr = c*32 + p*16 + rK, ch = 2*kk + cK;
                    uint32_t b0, b1, b2, b3;
                    ldsm_x4(b0, b1, b2, b3, stg + swoff(rr, ch));          // Kh
                    MMA(Sd[0][2*p],   Ah[0][kk], b0, b1);
                    MMA(Sd[1][2*p],   Ah[1][kk], b0, b1);
                    MMA(Sd[0][2*p+1], Ah[0][kk], b2, b3);
                    MMA(Sd[1][2*p+1], Ah[1][kk], b2, b3);
                    MMA(Sd[0][2*p],   Al[0][kk], b0, b1);
                    MMA(Sd[1][2*p],   Al[1][kk], b0, b1);
                    MMA(Sd[0][2*p+1], Al[0][kk], b2, b3);
                    MMA(Sd[1][2*p+1], Al[1][kk], b2, b3);
                    ldsm_x4(b0, b1, b2, b3, stg + 8192 + swoff(rr, ch));   // Kl
                    MMA(Sd[0][2*p],   Ah[0][kk], b0, b1);
                    MMA(Sd[1][2*p],   Ah[1][kk], b0, b1);
                    MMA(Sd[0][2*p+1], Ah[0][kk], b2, b3);
                    MMA(Sd[1][2*p+1], Ah[1][kk], b2, b3);
                }

            uint32_t Ph[2][2][4], Pl2[2][2][4];
            #pragma unroll
            for (int mi = 0; mi < 2; mi++)
                #pragma unroll
                for (int u = 0; u < 2; u++) {
                    uint4 mwv = mw[mi*2 + u];
                    unsigned wq = (c == 0) ? mwv.x : (c == 1) ? mwv.y : (c == 2) ? mwv.z : mwv.w;
                    float lacc = 0.f;
                    #pragma unroll
                    for (int j = 0; j < 4; j++) {
                        int bp = 8*j + 2*cq;
                        float p0 = ((wq >> bp) & 1u)     ? 0.f : ex2f(Sd[mi][j][2*u]);
                        float p1 = ((wq >> (bp+1)) & 1u) ? 0.f : ex2f(Sd[mi][j][2*u+1]);
                        lacc += p0 + p1;
                        uint32_t ph = cvtpk_bf16x2(p1, p0);
                        float f0 = __uint_as_float(ph << 16);
                        float f1 = __uint_as_float(ph & 0xffff0000u);
                        uint32_t pl = cvtpk_bf16x2(p1 - f1, p0 - f0);
                        Ph[mi][j >> 1][(j & 1)*2 + u]  = ph;
                        Pl2[mi][j >> 1][(j & 1)*2 + u] = pl;
                    }
                    ls[mi*2 + u] += lacc;
                }

            #pragma unroll
            for (int kk = 0; kk < 2; kk++)
                #pragma unroll
                for (int p = 0; p < 2; p++) {
                    int rr = c*32 + kk*16 + rV, ch = 2*p + cV;
                    uint32_t b0, b1, b2, b3;
                    ldsm_x4_t(b0, b1, b2, b3, stg + 16384 + swoff(rr, ch)); // Vh
                    MMA(Od[0][2*p],   Ph[0][kk], b0, b1);
                    MMA(Od[1][2*p],   Ph[1][kk], b0, b1);
                    MMA(Od[0][2*p+1], Ph[0][kk], b2, b3);
                    MMA(Od[1][2*p+1], Ph[1][kk], b2, b3);
                    MMA(Od[0][2*p],   Pl2[0][kk], b0, b1);
                    MMA(Od[1][2*p],   Pl2[1][kk], b0, b1);
                    MMA(Od[0][2*p+1], Pl2[0][kk], b2, b3);
                    MMA(Od[1][2*p+1], Pl2[1][kk], b2, b3);
                    ldsm_x4_t(b0, b1, b2, b3, stg + 24576 + swoff(rr, ch)); // Vl
                    MMA(Od[0][2*p],   Ph[0][kk], b0, b1);
                    MMA(Od[1][2*p],   Ph[1][kk], b0, b1);
                    MMA(Od[0][2*p+1], Ph[0][kk], b2, b3);
                    MMA(Od[1][2*p+1], Ph[1][kk], b2, b3);
                }
        }
        __syncthreads();
    }

    #pragma unroll
    for (int i = 0; i < 4; i++) {
        ls[i] += __shfl_xor_sync(0xffffffffu, ls[i], 1);
        ls[i] += __shfl_xor_sync(0xffffffffu, ls[i], 2);
        ls[i] = 1.f / ls[i];
    }
    #pragma unroll
    for (int mi = 0; mi < 2; mi++)
        #pragma unroll
        for (int u = 0; u < 2; u++) {
            int row = qbase + g + 16*mi + 8*u;
            float inv = ls[mi*2 + u];
            #pragma unroll
            for (int j = 0; j < 4; j++) {
                float2 v = make_float2(Od[mi][j][2*u] * inv, Od[mi][j][2*u+1] * inv);
                *(float2*)(g_A + ((size_t)(b * S_ + row)) * DM + h * DH + 8*j + 2*cq) = v;
            }
        }
}

// ============================================================================
extern "C" void kernel_launch(void* const* d_in, const int* in_sizes, int n_in,
                              void* d_out, int out_size)
{
    const float* q    = (const float*)d_in[0];
    const float* k    = (const float*)d_in[1];
    const float* v    = (const float*)d_in[2];
    const int*   mask = (const int*)d_in[3];
    const float* wq   = (const float*)d_in[4];
    const float* wk   = (const float*)d_in[5];
    const float* wv   = (const float*)d_in[6];
    const float* wo   = (const float*)d_in[7];

    const float qscale = 0.17677669529663688f * 1.4426950408889634f;
    const size_t NI = (size_t)B_ * S_ * DM;     // 2M elements per input
    const int NW = DM * DM;                      // 65536 per weight

    static int smem_set = 0;
    if (!smem_set) {
        cudaFuncSetAttribute(attn_fa, cudaFuncAttributeMaxDynamicSharedMemorySize, 2 * STG_BYTES);
        smem_set = 1;
    }

    __nv_bfloat16 *ih, *il, *wth, *wtl;
    cudaGetSymbolAddress((void**)&ih,  g_Ih);
    cudaGetSymbolAddress((void**)&il,  g_Il);
    cudaGetSymbolAddress((void**)&wth, g_Wth);
    cudaGetSymbolAddress((void**)&wtl, g_Wtl);

    // 1. split inputs + weights
    int cg = (int)(NI / 4 / 256);   // 2048 blocks
    conv_split<<<cg, 256>>>(q, ih + 0*NI, il + 0*NI);
    conv_split<<<cg, 256>>>(k, ih + 1*NI, il + 1*NI);
    conv_split<<<cg, 256>>>(v, ih + 2*NI, il + 2*NI);
    conv_wt<<<NW/256, 256>>>(wq, wth + 0*NW, wtl + 0*NW);
    conv_wt<<<NW/256, 256>>>(wk, wth + 1*NW, wtl + 1*NW);
    conv_wt<<<NW/256, 256>>>(wv, wth + 2*NW, wtl + 2*NW);

    // 2. tensor-core projections -> split hi/lo Q/K/V
    dim3 pg(DM / 64, (B_ * S_) / 64);   // (4, 128)
    pmma_proj<<<pg, 128>>>(ih + 0*NI, il + 0*NI, wth + 0*NW, wtl + 0*NW, qscale, 1);
    pmma_proj<<<pg, 128>>>(ih + 1*NI, il + 1*NI, wth + 1*NW, wtl + 1*NW, 1.f,    2);
    pmma_proj<<<pg, 128>>>(ih + 2*NI, il + 2*NI, wth + 2*NW, wtl + 2*NW, 1.f,    3);

    // 3. mask bits
    mask_compress<<<(int)((size_t)B_*S_*S_/4/256), 256>>>(mask);

    // 4. attention
    attn_fa<<<dim3(S_/128, H_, B_), 128, 2 * STG_BYTES>>>();

    // 5. out-projection
    sgemm_out<<<dim3(DM/64, (B_*S_)/64), 256>>>(wo, (float*)d_out);
}